// round 15
// baseline (speedup 1.0000x reference)
#include <cuda_runtime.h>

// Persistent STPN, R8/R14 structure (16 groups x 8 CTAs, CTA = 32 rows x 2
// batches, warp = 2 rows x 2 batches, u = w + f in registers).
// R15: the group-wait for step t+1 and the h(t)/x(t+1) loads are hoisted to
// right after publish(t); the shadow covers their latency, so pre is pure
// register math. Poll is per-warp (no second __syncthreads).

#define NCTA 128
#define NTHR 512
#define GSZ 8

namespace {
constexpr int kB = 32;
constexpr int kS = 64;
constexpr int kI = 256;
constexpr int kH = 256;
constexpr int kO = 128;
constexpr int kF = 512;
constexpr int kRows = 32;
}

typedef unsigned long long u64;

__device__ unsigned g_flags[NCTA];
__device__ float g_hbuf[3][kB * kH];

__device__ __forceinline__ unsigned ld_acq(const unsigned* p) {
  unsigned v;
  asm volatile("ld.acquire.gpu.u32 %0, [%1];" : "=r"(v) : "l"(p) : "memory");
  return v;
}
__device__ __forceinline__ void st_rel(unsigned* p, unsigned v) {
  asm volatile("st.release.gpu.u32 [%0], %1;" :: "l"(p), "r"(v) : "memory");
}
__device__ __forceinline__ u64 fma2(u64 a, u64 b, u64 c) {
  u64 d; asm("fma.rn.f32x2 %0, %1, %2, %3;" : "=l"(d) : "l"(a), "l"(b), "l"(c));
  return d;
}
__device__ __forceinline__ u64 mul2(u64 a, u64 b) {
  u64 d; asm("mul.rn.f32x2 %0, %1, %2;" : "=l"(d) : "l"(a), "l"(b));
  return d;
}
__device__ __forceinline__ u64 pack2(float lo, float hi) {
  u64 d; asm("mov.b64 %0, {%1, %2};" : "=l"(d) : "f"(lo), "f"(hi));
  return d;
}
__device__ __forceinline__ float2 unpack2(u64 v) {
  float2 r; asm("mov.b64 {%0, %1}, %2;" : "=f"(r.x), "=f"(r.y) : "l"(v));
  return r;
}
__device__ __forceinline__ float hsum(u64 v) {
  float2 a = unpack2(v);
  return a.x + a.y;
}
__device__ __forceinline__ void red4(float& a, float& b, float& c, float& d) {
#pragma unroll
  for (int off = 16; off; off >>= 1) {
    a += __shfl_xor_sync(0xffffffffu, a, off);
    b += __shfl_xor_sync(0xffffffffu, b, off);
    c += __shfl_xor_sync(0xffffffffu, c, off);
    d += __shfl_xor_sync(0xffffffffu, d, off);
  }
}
__device__ __forceinline__ float tanh_fast(float z) {
  float e = __expf(2.0f * z);
  return 1.0f - __fdividef(2.0f, e + 1.0f);
}

extern __shared__ float smem_dyn[];

__global__ void __launch_bounds__(NTHR, 1) stpn_kernel(
    const float* __restrict__ x,
    const float* __restrict__ W,
    const float* __restrict__ Lm,
    const float* __restrict__ Gm,
    const float* __restrict__ bias,
    const float* __restrict__ ow,
    const float* __restrict__ ob,
    float* __restrict__ out)
{
  float* sw = smem_dyn;
  float* sl = sw + kRows * kF;
  float* sg = sl + kRows * kF;
  __shared__ unsigned s_base;

  const int tid  = threadIdx.x;
  const int lane = tid & 31;
  const int wid  = tid >> 5;
  const int gid  = blockIdx.x >> 3;
  const int rank = blockIdx.x & 7;
  const int bA   = gid * 2;
  const int bB   = bA + 1;
  const int grow0 = rank * kRows;
  const int lr0  = 2 * wid;
  const int row0 = grow0 + lr0;

  for (int i = tid; i < kRows * kF; i += NTHR) {
    const int r = i >> 9, c = i & 511;
    sw[i] = W[(grow0 + r) * kF + c];
    sl[i] = Lm[(grow0 + r) * kF + c];
    sg[i] = Gm[(grow0 + r) * kF + c];
  }
  if (tid == 0) s_base = __ldcg(&g_flags[blockIdx.x]);
  const float bias0 = bias[row0];
  const float bias1 = bias[row0 + 1];
  __syncthreads();
  const unsigned base = s_base;

  const u64* swp0 = (const u64*)(sw + lr0 * kF);
  const u64* swp1 = (const u64*)(sw + (lr0 + 1) * kF);
  const u64* slp0 = (const u64*)(sl + lr0 * kF);
  const u64* slp1 = (const u64*)(sl + (lr0 + 1) * kF);
  const u64* sgp0 = (const u64*)(sg + lr0 * kF);
  const u64* sgp1 = (const u64*)(sg + (lr0 + 1) * kF);

  // u = w + f (f=0 initially)
  u64 uu[2][2][8];
#pragma unroll
  for (int q = 0; q < 8; ++q) {
    const int p = 64 * (q >> 1) + 2 * lane + (q & 1);
    const u64 w0 = swp0[p], w1 = swp1[p];
    uu[0][0][q] = w0; uu[0][1][q] = w0;
    uu[1][0][q] = w1; uu[1][1][q] = w1;
  }

  float iv[2][2];
  {
    u64 sp0 = mul2(uu[0][0][0], uu[0][0][0]);
    u64 sp1 = mul2(uu[1][0][0], uu[1][0][0]);
#pragma unroll
    for (int q = 1; q < 8; ++q) {
      sp0 = fma2(uu[0][0][q], uu[0][0][q], sp0);
      sp1 = fma2(uu[1][0][q], uu[1][0][q], sp1);
    }
    float s0 = hsum(sp0), s1 = hsum(sp1), s2 = 0.f, s3 = 0.f;
    red4(s0, s1, s2, s3);
    iv[0][0] = rsqrtf(s0); iv[0][1] = iv[0][0];
    iv[1][0] = rsqrtf(s1); iv[1][1] = iv[1][0];
  }

  float hn[2][2] = {{0.f, 0.f}, {0.f, 0.f}};

  // ti registers for the CURRENT step: x(t) and h(t-1)
  u64 ta0, ta1, ta2, ta3, tb0, tb1, tb2, tb3;
  u64 ha0 = 0, ha1 = 0, ha2 = 0, ha3 = 0;
  u64 hb0 = 0, hb1 = 0, hb2 = 0, hb3 = 0;
  {
    const u64* xpa = (const u64*)(x + (size_t)bA * kS * kI);
    const u64* xpb = (const u64*)(x + (size_t)bB * kS * kI);
    ta0 = xpa[2 * lane];      ta1 = xpa[2 * lane + 1];
    ta2 = xpa[64 + 2 * lane]; ta3 = xpa[64 + 2 * lane + 1];
    tb0 = xpb[2 * lane];      tb1 = xpb[2 * lane + 1];
    tb2 = xpb[64 + 2 * lane]; tb3 = xpb[64 + 2 * lane + 1];
  }

  for (int t = 0; t < kS; ++t) {
    // ---- pre(t): pure register math ----
    {
      u64 a00 = mul2(ta0, uu[0][0][0]);  u64 a10 = mul2(ta0, uu[1][0][0]);
      u64 a01 = mul2(tb0, uu[0][1][0]);  u64 a11 = mul2(tb0, uu[1][1][0]);
      a00 = fma2(ta1, uu[0][0][1], a00); a10 = fma2(ta1, uu[1][0][1], a10);
      a01 = fma2(tb1, uu[0][1][1], a01); a11 = fma2(tb1, uu[1][1][1], a11);
      a00 = fma2(ta2, uu[0][0][2], a00); a10 = fma2(ta2, uu[1][0][2], a10);
      a01 = fma2(tb2, uu[0][1][2], a01); a11 = fma2(tb2, uu[1][1][2], a11);
      a00 = fma2(ta3, uu[0][0][3], a00); a10 = fma2(ta3, uu[1][0][3], a10);
      a01 = fma2(tb3, uu[0][1][3], a01); a11 = fma2(tb3, uu[1][1][3], a11);
      a00 = fma2(ha0, uu[0][0][4], a00); a10 = fma2(ha0, uu[1][0][4], a10);
      a01 = fma2(hb0, uu[0][1][4], a01); a11 = fma2(hb0, uu[1][1][4], a11);
      a00 = fma2(ha1, uu[0][0][5], a00); a10 = fma2(ha1, uu[1][0][5], a10);
      a01 = fma2(hb1, uu[0][1][5], a01); a11 = fma2(hb1, uu[1][1][5], a11);
      a00 = fma2(ha2, uu[0][0][6], a00); a10 = fma2(ha2, uu[1][0][6], a10);
      a01 = fma2(hb2, uu[0][1][6], a01); a11 = fma2(hb2, uu[1][1][6], a11);
      a00 = fma2(ha3, uu[0][0][7], a00); a10 = fma2(ha3, uu[1][0][7], a10);
      a01 = fma2(hb3, uu[0][1][7], a01); a11 = fma2(hb3, uu[1][1][7], a11);
      float p00 = hsum(a00), p01 = hsum(a01);
      float p10 = hsum(a10), p11 = hsum(a11);
      red4(p00, p01, p10, p11);
      hn[0][0] = tanh_fast(fmaf(p00, iv[0][0], bias0));
      hn[0][1] = tanh_fast(fmaf(p01, iv[0][1], bias0));
      hn[1][0] = tanh_fast(fmaf(p10, iv[1][0], bias1));
      hn[1][1] = tanh_fast(fmaf(p11, iv[1][1], bias1));
    }

    // ---- publish h(t) ----
    const int wb = t % 3;
    if (lane == 0) {
      __stcg((u64*)&g_hbuf[wb][bA * kH + row0], pack2(hn[0][0], hn[1][0]));
      __stcg((u64*)&g_hbuf[wb][bB * kH + row0], pack2(hn[0][1], hn[1][1]));
    }
    __syncthreads();   // all warps' h-stores ordered before the flag release
    if (tid == 0) st_rel(&g_flags[blockIdx.x], base + (unsigned)(t + 1));

    // ---- hoisted wait + loads for step t+1 (latency covered by shadow) ----
    u64 nha0 = 0, nha1 = 0, nha2 = 0, nha3 = 0;
    u64 nhb0 = 0, nhb1 = 0, nhb2 = 0, nhb3 = 0;
    u64 nta0 = 0, nta1 = 0, nta2 = 0, nta3 = 0;
    u64 ntb0 = 0, ntb1 = 0, ntb2 = 0, ntb3 = 0;
    if (t + 1 < kS) {
      // per-warp poll: lanes 0..7 each watch one group flag
      {
        const unsigned tg = base + (unsigned)(t + 1);
        const unsigned* fp = &g_flags[gid * GSZ + lane];
        for (;;) {
          bool ok = (lane >= GSZ) || ((int)(ld_acq(fp) - tg) >= 0);
          if (__all_sync(0xffffffffu, ok)) break;
        }
      }
      // h(t) from the slot just written; x(t+1)
      const u64* hpa = (const u64*)(&g_hbuf[wb][bA * kH]);
      const u64* hpb = (const u64*)(&g_hbuf[wb][bB * kH]);
      nha0 = __ldcg(hpa + 2 * lane);      nha1 = __ldcg(hpa + 2 * lane + 1);
      nha2 = __ldcg(hpa + 64 + 2 * lane); nha3 = __ldcg(hpa + 64 + 2 * lane + 1);
      nhb0 = __ldcg(hpb + 2 * lane);      nhb1 = __ldcg(hpb + 2 * lane + 1);
      nhb2 = __ldcg(hpb + 64 + 2 * lane); nhb3 = __ldcg(hpb + 64 + 2 * lane + 1);
      const u64* xpa = (const u64*)(x + ((size_t)bA * kS + t + 1) * kI);
      const u64* xpb = (const u64*)(x + ((size_t)bB * kS + t + 1) * kI);
      nta0 = xpa[2 * lane];      nta1 = xpa[2 * lane + 1];
      nta2 = xpa[64 + 2 * lane]; nta3 = xpa[64 + 2 * lane + 1];
      ntb0 = xpb[2 * lane];      ntb1 = xpb[2 * lane + 1];
      ntb2 = xpb[64 + 2 * lane]; ntb3 = xpb[64 + 2 * lane + 1];
    }

    // ---- shadow(t): u' = w + (lam*iv)*(u-w) + (gam*hn)*ti ; sq ----
    {
      const u64 n1 = pack2(-1.0f, -1.0f);
      u64 sq[2][2] = {{0, 0}, {0, 0}};
#pragma unroll
      for (int k = 0; k < 4; ++k) {
        const int p = 64 * k + 2 * lane;
        const u64 w00 = swp0[p], w01 = swp0[p + 1];
        const u64 w10 = swp1[p], w11 = swp1[p + 1];
        const u64 l00 = slp0[p], l01 = slp0[p + 1];
        const u64 l10 = slp1[p], l11 = slp1[p + 1];
        const u64 g00 = sgp0[p], g01 = sgp0[p + 1];
        const u64 g10 = sgp1[p], g11 = sgp1[p + 1];
#pragma unroll
        for (int b = 0; b < 2; ++b) {
          u64 ti0, ti1;
          if (k == 0)      { ti0 = b ? tb0 : ta0; ti1 = b ? tb1 : ta1; }
          else if (k == 1) { ti0 = b ? tb2 : ta2; ti1 = b ? tb3 : ta3; }
          else if (k == 2) { ti0 = b ? hb0 : ha0; ti1 = b ? hb1 : ha1; }
          else             { ti0 = b ? hb2 : ha2; ti1 = b ? hb3 : ha3; }
#pragma unroll
          for (int r = 0; r < 2; ++r) {
            const u64 ivp = pack2(iv[r][b], iv[r][b]);
            const u64 ghp = pack2(hn[r][b], hn[r][b]);
            const u64 wA = r ? w10 : w00, wB = r ? w11 : w01;
            const u64 lA = r ? l10 : l00, lB = r ? l11 : l01;
            const u64 gA = r ? g10 : g00, gB = r ? g11 : g01;
            u64& Ua = uu[r][b][2 * k];
            u64& Ub = uu[r][b][2 * k + 1];
            {
              const u64 a = mul2(lA, ivp);
              const u64 d = fma2(n1, wA, Ua);
              const u64 e = fma2(mul2(gA, ghp), ti0, wA);
              Ua = fma2(a, d, e);
              sq[r][b] = fma2(Ua, Ua, sq[r][b]);
            }
            {
              const u64 a = mul2(lB, ivp);
              const u64 d = fma2(n1, wB, Ub);
              const u64 e = fma2(mul2(gB, ghp), ti1, wB);
              Ub = fma2(a, d, e);
              sq[r][b] = fma2(Ub, Ub, sq[r][b]);
            }
          }
        }
      }
      float s00 = hsum(sq[0][0]), s01 = hsum(sq[0][1]);
      float s10 = hsum(sq[1][0]), s11 = hsum(sq[1][1]);
      red4(s00, s01, s10, s11);
      iv[0][0] = rsqrtf(s00); iv[0][1] = rsqrtf(s01);
      iv[1][0] = rsqrtf(s10); iv[1][1] = rsqrtf(s11);
    }

    // ---- rotate ti registers for the next step ----
    ta0 = nta0; ta1 = nta1; ta2 = nta2; ta3 = nta3;
    tb0 = ntb0; tb1 = ntb1; tb2 = ntb2; tb3 = ntb3;
    ha0 = nha0; ha1 = nha1; ha2 = nha2; ha3 = nha3;
    hb0 = nhb0; hb1 = nhb1; hb2 = nhb2; hb3 = nhb3;
  }

  // ---------------- epilogue ----------------
  {
    const u64 n1 = pack2(-1.0f, -1.0f);
    u64* fout = (u64*)(out + kB * kO + kB * kH);
#pragma unroll
    for (int r = 0; r < 2; ++r) {
      const u64* swr = r ? swp1 : swp0;
#pragma unroll
      for (int b = 0; b < 2; ++b) {
        const int bb = b ? bB : bA;
        u64* rowp = fout + (size_t)(bb * kH + row0 + r) * (kF / 2);
#pragma unroll
        for (int q = 0; q < 8; ++q) {
          const int p = 64 * (q >> 1) + 2 * lane + (q & 1);
          rowp[p] = fma2(n1, swr[p], uu[r][b][q]);
        }
      }
    }
  }
  if (lane == 0) {
    *(u64*)&out[kB * kO + bA * kH + row0] = pack2(hn[0][0], hn[1][0]);
    *(u64*)&out[kB * kO + bB * kH + row0] = pack2(hn[0][1], hn[1][1]);
  }

  // tag_space: ranks 0,1 compute batches bA,bB after own group finishes
  if (rank < 2) {
    if (tid < GSZ) {
      const unsigned tg = base + (unsigned)kS;
      const unsigned* fp = &g_flags[gid * GSZ + tid];
      while ((int)(ld_acq(fp) - tg) < 0) { }
    }
    __syncthreads();
    const int bb = rank ? bB : bA;
    const float* hf = &g_hbuf[(kS - 1) % 3][bb * kH];
#pragma unroll
    for (int j = 0; j < 8; ++j) {
      const int oo = wid * 8 + j;
      float p = 0.f;
#pragma unroll
      for (int mm = 0; mm < 8; ++mm) {
        p += __ldcg(&hf[lane + 32 * mm]) * ow[oo * kH + lane + 32 * mm];
      }
#pragma unroll
      for (int off = 16; off; off >>= 1) p += __shfl_xor_sync(0xffffffffu, p, off);
      if (lane == 0) out[bb * kO + oo] = p + ob[oo];
    }
  }
}

extern "C" void kernel_launch(void* const* d_in, const int* in_sizes, int n_in,
                              void* d_out, int out_size) {
  (void)in_sizes; (void)n_in; (void)out_size;
  const int smem_bytes = 3 * kRows * kF * (int)sizeof(float);  // 196608
  cudaFuncSetAttribute(stpn_kernel,
                       cudaFuncAttributeMaxDynamicSharedMemorySize, smem_bytes);
  stpn_kernel<<<NCTA, NTHR, smem_bytes>>>(
      (const float*)d_in[0],
      (const float*)d_in[1],
      (const float*)d_in[2],
      (const float*)d_in[3],
      (const float*)d_in[4],
      (const float*)d_in[5],
      (const float*)d_in[6],
      (float*)d_out);
}

// round 16
// speedup vs baseline: 3.5231x; 3.5231x over previous
#include <cuda_runtime.h>

// Persistent STPN, R8/R14 structure (16 groups x 8 CTAs, CTA = 32 rows x 2
// batches, warp = 2 rows x 2 batches, u = w + f in registers).
// R16: ti (x(t) and h(t-1)) staged cooperatively through shared memory --
// one 8B global load per thread per step instead of 16 per warp; the flag
// poll folds into the h-staging threads (each polls its source CTA's flag).

#define NCTA 128
#define NTHR 512
#define GSZ 8

namespace {
constexpr int kB = 32;
constexpr int kS = 64;
constexpr int kI = 256;
constexpr int kH = 256;
constexpr int kO = 128;
constexpr int kF = 512;
constexpr int kRows = 32;
}

typedef unsigned long long u64;

__device__ unsigned g_flags[NCTA];
__device__ float g_hbuf[3][kB * kH];

__device__ __forceinline__ unsigned ld_acq(const unsigned* p) {
  unsigned v;
  asm volatile("ld.acquire.gpu.u32 %0, [%1];" : "=r"(v) : "l"(p) : "memory");
  return v;
}
__device__ __forceinline__ void st_rel(unsigned* p, unsigned v) {
  asm volatile("st.release.gpu.u32 [%0], %1;" :: "l"(p), "r"(v) : "memory");
}
__device__ __forceinline__ u64 fma2(u64 a, u64 b, u64 c) {
  u64 d; asm("fma.rn.f32x2 %0, %1, %2, %3;" : "=l"(d) : "l"(a), "l"(b), "l"(c));
  return d;
}
__device__ __forceinline__ u64 mul2(u64 a, u64 b) {
  u64 d; asm("mul.rn.f32x2 %0, %1, %2;" : "=l"(d) : "l"(a), "l"(b));
  return d;
}
__device__ __forceinline__ u64 pack2(float lo, float hi) {
  u64 d; asm("mov.b64 %0, {%1, %2};" : "=l"(d) : "f"(lo), "f"(hi));
  return d;
}
__device__ __forceinline__ float2 unpack2(u64 v) {
  float2 r; asm("mov.b64 {%0, %1}, %2;" : "=f"(r.x), "=f"(r.y) : "l"(v));
  return r;
}
__device__ __forceinline__ float hsum(u64 v) {
  float2 a = unpack2(v);
  return a.x + a.y;
}
__device__ __forceinline__ void red4(float& a, float& b, float& c, float& d) {
#pragma unroll
  for (int off = 16; off; off >>= 1) {
    a += __shfl_xor_sync(0xffffffffu, a, off);
    b += __shfl_xor_sync(0xffffffffu, b, off);
    c += __shfl_xor_sync(0xffffffffu, c, off);
    d += __shfl_xor_sync(0xffffffffu, d, off);
  }
}
__device__ __forceinline__ float tanh_fast(float z) {
  float e = __expf(2.0f * z);
  return 1.0f - __fdividef(2.0f, e + 1.0f);
}

extern __shared__ float smem_dyn[];

__global__ void __launch_bounds__(NTHR, 1) stpn_kernel(
    const float* __restrict__ x,
    const float* __restrict__ W,
    const float* __restrict__ Lm,
    const float* __restrict__ Gm,
    const float* __restrict__ bias,
    const float* __restrict__ ow,
    const float* __restrict__ ob,
    float* __restrict__ out)
{
  float* sw = smem_dyn;
  float* sl = sw + kRows * kF;
  float* sg = sl + kRows * kF;
  __shared__ __align__(16) u64 s_ti[2][256];  // [batch][0..127 x | 128..255 h]
  __shared__ unsigned s_base;

  const int tid  = threadIdx.x;
  const int lane = tid & 31;
  const int wid  = tid >> 5;
  const int gid  = blockIdx.x >> 3;
  const int rank = blockIdx.x & 7;
  const int bA   = gid * 2;
  const int bB   = bA + 1;
  const int grow0 = rank * kRows;
  const int lr0  = 2 * wid;
  const int row0 = grow0 + lr0;

  for (int i = tid; i < kRows * kF; i += NTHR) {
    const int r = i >> 9, c = i & 511;
    sw[i] = W[(grow0 + r) * kF + c];
    sl[i] = Lm[(grow0 + r) * kF + c];
    sg[i] = Gm[(grow0 + r) * kF + c];
  }
  if (tid == 0) s_base = __ldcg(&g_flags[blockIdx.x]);
  const float bias0 = bias[row0];
  const float bias1 = bias[row0 + 1];
  __syncthreads();
  const unsigned base = s_base;

  const u64* swp0 = (const u64*)(sw + lr0 * kF);
  const u64* swp1 = (const u64*)(sw + (lr0 + 1) * kF);
  const u64* slp0 = (const u64*)(sl + lr0 * kF);
  const u64* slp1 = (const u64*)(sl + (lr0 + 1) * kF);
  const u64* sgp0 = (const u64*)(sg + lr0 * kF);
  const u64* sgp1 = (const u64*)(sg + (lr0 + 1) * kF);

  // u = w + f (f=0 initially)
  u64 uu[2][2][8];
#pragma unroll
  for (int q = 0; q < 8; ++q) {
    const int p = 64 * (q >> 1) + 2 * lane + (q & 1);
    const u64 w0 = swp0[p], w1 = swp1[p];
    uu[0][0][q] = w0; uu[0][1][q] = w0;
    uu[1][0][q] = w1; uu[1][1][q] = w1;
  }

  float iv[2][2];
  {
    u64 sp0 = mul2(uu[0][0][0], uu[0][0][0]);
    u64 sp1 = mul2(uu[1][0][0], uu[1][0][0]);
#pragma unroll
    for (int q = 1; q < 8; ++q) {
      sp0 = fma2(uu[0][0][q], uu[0][0][q], sp0);
      sp1 = fma2(uu[1][0][q], uu[1][0][q], sp1);
    }
    float s0 = hsum(sp0), s1 = hsum(sp1), s2 = 0.f, s3 = 0.f;
    red4(s0, s1, s2, s3);
    iv[0][0] = rsqrtf(s0); iv[0][1] = iv[0][0];
    iv[1][0] = rsqrtf(s1); iv[1][1] = iv[1][0];
  }

  float hn[2][2] = {{0.f, 0.f}, {0.f, 0.f}};

  for (int t = 0; t < kS; ++t) {
    const int wb = t % 3;
    const int rbs = (t + 2) % 3;   // slot of h(t-1) for t>0

    // ---- stage ti: x(t) by tids 0..255, h(t-1) by tids 256..511 ----
    {
      if (tid < 256) {
        const int b = tid >> 7, j = tid & 127;
        const u64* xp = (const u64*)(x + ((size_t)(bA + b) * kS + t) * kI);
        s_ti[b][j] = xp[j];
      } else {
        const int p = tid - 256;
        const int b = p >> 7, j = p & 127;
        if (t > 0) {
          // poll the source CTA's flag (rows 2j,2j+1 -> rank j>>4)
          const unsigned tg = base + (unsigned)t;
          const unsigned* fp = &g_flags[gid * GSZ + (j >> 4)];
          while ((int)(ld_acq(fp) - tg) < 0) { }
          s_ti[b][128 + j] =
              __ldcg((const u64*)(&g_hbuf[rbs][(bA + b) * kH]) + j);
        } else {
          s_ti[b][128 + j] = 0;
        }
      }
    }
    __syncthreads();

    // ---- load ti into registers (LDS; persist into shadow) ----
    const u64* sA = &s_ti[0][0];
    const u64* sB = &s_ti[1][0];
    const u64 ta0 = sA[2 * lane],       ta1 = sA[2 * lane + 1];
    const u64 ta2 = sA[64 + 2 * lane],  ta3 = sA[64 + 2 * lane + 1];
    const u64 ha0 = sA[128 + 2 * lane], ha1 = sA[128 + 2 * lane + 1];
    const u64 ha2 = sA[192 + 2 * lane], ha3 = sA[192 + 2 * lane + 1];
    const u64 tb0 = sB[2 * lane],       tb1 = sB[2 * lane + 1];
    const u64 tb2 = sB[64 + 2 * lane],  tb3 = sB[64 + 2 * lane + 1];
    const u64 hb0 = sB[128 + 2 * lane], hb1 = sB[128 + 2 * lane + 1];
    const u64 hb2 = sB[192 + 2 * lane], hb3 = sB[192 + 2 * lane + 1];

    // ---- pre = ti . u ----
    {
      u64 a00 = mul2(ta0, uu[0][0][0]);  u64 a10 = mul2(ta0, uu[1][0][0]);
      u64 a01 = mul2(tb0, uu[0][1][0]);  u64 a11 = mul2(tb0, uu[1][1][0]);
      a00 = fma2(ta1, uu[0][0][1], a00); a10 = fma2(ta1, uu[1][0][1], a10);
      a01 = fma2(tb1, uu[0][1][1], a01); a11 = fma2(tb1, uu[1][1][1], a11);
      a00 = fma2(ta2, uu[0][0][2], a00); a10 = fma2(ta2, uu[1][0][2], a10);
      a01 = fma2(tb2, uu[0][1][2], a01); a11 = fma2(tb2, uu[1][1][2], a11);
      a00 = fma2(ta3, uu[0][0][3], a00); a10 = fma2(ta3, uu[1][0][3], a10);
      a01 = fma2(tb3, uu[0][1][3], a01); a11 = fma2(tb3, uu[1][1][3], a11);
      a00 = fma2(ha0, uu[0][0][4], a00); a10 = fma2(ha0, uu[1][0][4], a10);
      a01 = fma2(hb0, uu[0][1][4], a01); a11 = fma2(hb0, uu[1][1][4], a11);
      a00 = fma2(ha1, uu[0][0][5], a00); a10 = fma2(ha1, uu[1][0][5], a10);
      a01 = fma2(hb1, uu[0][1][5], a01); a11 = fma2(hb1, uu[1][1][5], a11);
      a00 = fma2(ha2, uu[0][0][6], a00); a10 = fma2(ha2, uu[1][0][6], a10);
      a01 = fma2(hb2, uu[0][1][6], a01); a11 = fma2(hb2, uu[1][1][6], a11);
      a00 = fma2(ha3, uu[0][0][7], a00); a10 = fma2(ha3, uu[1][0][7], a10);
      a01 = fma2(hb3, uu[0][1][7], a01); a11 = fma2(hb3, uu[1][1][7], a11);
      float p00 = hsum(a00), p01 = hsum(a01);
      float p10 = hsum(a10), p11 = hsum(a11);
      red4(p00, p01, p10, p11);
      hn[0][0] = tanh_fast(fmaf(p00, iv[0][0], bias0));
      hn[0][1] = tanh_fast(fmaf(p01, iv[0][1], bias0));
      hn[1][0] = tanh_fast(fmaf(p10, iv[1][0], bias1));
      hn[1][1] = tanh_fast(fmaf(p11, iv[1][1], bias1));
    }

    // ---- publish h(t) ----
    if (lane == 0) {
      __stcg((u64*)&g_hbuf[wb][bA * kH + row0], pack2(hn[0][0], hn[1][0]));
      __stcg((u64*)&g_hbuf[wb][bB * kH + row0], pack2(hn[0][1], hn[1][1]));
    }
    __syncthreads();
    if (tid == 0) st_rel(&g_flags[blockIdx.x], base + (unsigned)(t + 1));

    // ---- shadow: u' = w + (lam*iv)*(u-w) + (gam*hn)*ti ; accumulate sq ----
    {
      const u64 n1 = pack2(-1.0f, -1.0f);
      u64 sq[2][2] = {{0, 0}, {0, 0}};
#pragma unroll
      for (int k = 0; k < 4; ++k) {
        const int p = 64 * k + 2 * lane;
        const u64 w00 = swp0[p], w01 = swp0[p + 1];
        const u64 w10 = swp1[p], w11 = swp1[p + 1];
        const u64 l00 = slp0[p], l01 = slp0[p + 1];
        const u64 l10 = slp1[p], l11 = slp1[p + 1];
        const u64 g00 = sgp0[p], g01 = sgp0[p + 1];
        const u64 g10 = sgp1[p], g11 = sgp1[p + 1];
#pragma unroll
        for (int b = 0; b < 2; ++b) {
          u64 ti0, ti1;
          if (k == 0)      { ti0 = b ? tb0 : ta0; ti1 = b ? tb1 : ta1; }
          else if (k == 1) { ti0 = b ? tb2 : ta2; ti1 = b ? tb3 : ta3; }
          else if (k == 2) { ti0 = b ? hb0 : ha0; ti1 = b ? hb1 : ha1; }
          else             { ti0 = b ? hb2 : ha2; ti1 = b ? hb3 : ha3; }
#pragma unroll
          for (int r = 0; r < 2; ++r) {
            const u64 ivp = pack2(iv[r][b], iv[r][b]);
            const u64 ghp = pack2(hn[r][b], hn[r][b]);
            const u64 wA = r ? w10 : w00, wB = r ? w11 : w01;
            const u64 lA = r ? l10 : l00, lB = r ? l11 : l01;
            const u64 gA = r ? g10 : g00, gB = r ? g11 : g01;
            u64& Ua = uu[r][b][2 * k];
            u64& Ub = uu[r][b][2 * k + 1];
            {
              const u64 a = mul2(lA, ivp);
              const u64 d = fma2(n1, wA, Ua);
              const u64 e = fma2(mul2(gA, ghp), ti0, wA);
              Ua = fma2(a, d, e);
              sq[r][b] = fma2(Ua, Ua, sq[r][b]);
            }
            {
              const u64 a = mul2(lB, ivp);
              const u64 d = fma2(n1, wB, Ub);
              const u64 e = fma2(mul2(gB, ghp), ti1, wB);
              Ub = fma2(a, d, e);
              sq[r][b] = fma2(Ub, Ub, sq[r][b]);
            }
          }
        }
      }
      float s00 = hsum(sq[0][0]), s01 = hsum(sq[0][1]);
      float s10 = hsum(sq[1][0]), s11 = hsum(sq[1][1]);
      red4(s00, s01, s10, s11);
      iv[0][0] = rsqrtf(s00); iv[0][1] = rsqrtf(s01);
      iv[1][0] = rsqrtf(s10); iv[1][1] = rsqrtf(s11);
    }
  }

  // ---------------- epilogue ----------------
  {
    const u64 n1 = pack2(-1.0f, -1.0f);
    u64* fout = (u64*)(out + kB * kO + kB * kH);
#pragma unroll
    for (int r = 0; r < 2; ++r) {
      const u64* swr = r ? swp1 : swp0;
#pragma unroll
      for (int b = 0; b < 2; ++b) {
        const int bb = b ? bB : bA;
        u64* rowp = fout + (size_t)(bb * kH + row0 + r) * (kF / 2);
#pragma unroll
        for (int q = 0; q < 8; ++q) {
          const int p = 64 * (q >> 1) + 2 * lane + (q & 1);
          rowp[p] = fma2(n1, swr[p], uu[r][b][q]);
        }
      }
    }
  }
  if (lane == 0) {
    *(u64*)&out[kB * kO + bA * kH + row0] = pack2(hn[0][0], hn[1][0]);
    *(u64*)&out[kB * kO + bB * kH + row0] = pack2(hn[0][1], hn[1][1]);
  }

  // tag_space: ranks 0,1 compute batches bA,bB after own group finishes
  if (rank < 2) {
    if (tid < GSZ) {
      const unsigned tg = base + (unsigned)kS;
      const unsigned* fp = &g_flags[gid * GSZ + tid];
      while ((int)(ld_acq(fp) - tg) < 0) { }
    }
    __syncthreads();
    const int bb = rank ? bB : bA;
    const float* hf = &g_hbuf[(kS - 1) % 3][bb * kH];
#pragma unroll
    for (int j = 0; j < 8; ++j) {
      const int oo = wid * 8 + j;
      float p = 0.f;
#pragma unroll
      for (int mm = 0; mm < 8; ++mm) {
        p += __ldcg(&hf[lane + 32 * mm]) * ow[oo * kH + lane + 32 * mm];
      }
#pragma unroll
      for (int off = 16; off; off >>= 1) p += __shfl_xor_sync(0xffffffffu, p, off);
      if (lane == 0) out[bb * kO + oo] = p + ob[oo];
    }
  }
}

extern "C" void kernel_launch(void* const* d_in, const int* in_sizes, int n_in,
                              void* d_out, int out_size) {
  (void)in_sizes; (void)n_in; (void)out_size;
  const int smem_bytes = 3 * kRows * kF * (int)sizeof(float);  // 196608
  cudaFuncSetAttribute(stpn_kernel,
                       cudaFuncAttributeMaxDynamicSharedMemorySize, smem_bytes);
  stpn_kernel<<<NCTA, NTHR, smem_bytes>>>(
      (const float*)d_in[0],
      (const float*)d_in[1],
      (const float*)d_in[2],
      (const float*)d_in[3],
      (const float*)d_in[4],
      (const float*)d_in[5],
      (const float*)d_in[6],
      (float*)d_out);
}